// round 10
// baseline (speedup 1.0000x reference)
#include <cuda_runtime.h>
#include <cuda_fp16.h>
#include <cstdint>

// ----------------------------------------------------------------------------
// diff_attention: B=8, S=2048, D=1024 — HMMA (mma.sync) optimized.
// tcgen05 is NOT available on this harness's ptxas target (sm_103, no 'a').
//
// Math simplifications (proved from the reference):
//  * softmax(A1) == 1/S exactly -> out = softmax(A2) @ V - (alpha/S)*colsum(V)
//  * V = vconst[b] + X2 @ Wv[D:],  vconst[b] = X1[b] @ Wv[:D] + bv
//
// GEMM: TN (B stored [n][k] K-major), CTA tile 128x256, warp tile 64x64,
// BK=32, 3-stage cp.async ring with ONE __syncthreads per k-tile.
// Logits are fp16, written into g_P and softmaxed IN-PLACE (no fp32 logits).
// ----------------------------------------------------------------------------

#define DEVINL __device__ __forceinline__

static constexpr int B = 8;
static constexpr int S = 2048;
static constexpr int D = 1024;

// ---------------- device scratch ---------------------------------------------
__device__ __half g_Xh[B * S * D];            // 32 MB
__device__ __half g_Wt[3 * D * D];            //  6 MB  W^T [n][k]: Wq2,Wk2,Wv_bot
__device__ __half g_Qh[B * S * D];            // 32 MB
__device__ __half g_Kh[B * S * D];            // 32 MB
__device__ __half g_Vh[B * S * D];            // 32 MB  V [s][d]
__device__ __half g_VhT[B * S * D];           // 32 MB  V^T [d][s]
__device__ float  g_vconst[B * D];
__device__ float  g_corr[B * D];
__device__ __half g_P[(long)B * S * S];       // 64 MB: logits then probs (in-place)

// ---------------- PTX helpers -------------------------------------------------
DEVINL uint32_t smem_u32(const void* p) {
    return (uint32_t)__cvta_generic_to_shared(p);
}
DEVINL void ldm_x4(uint32_t& r0, uint32_t& r1, uint32_t& r2, uint32_t& r3, uint32_t a) {
    asm volatile("ldmatrix.sync.aligned.m8n8.x4.shared.b16 {%0,%1,%2,%3},[%4];\n"
                 : "=r"(r0), "=r"(r1), "=r"(r2), "=r"(r3) : "r"(a));
}
DEVINL void ldm_x2(uint32_t& r0, uint32_t& r1, uint32_t a) {
    asm volatile("ldmatrix.sync.aligned.m8n8.x2.shared.b16 {%0,%1},[%2];\n"
                 : "=r"(r0), "=r"(r1) : "r"(a));
}
DEVINL void mma16816(float c[4], uint32_t a0, uint32_t a1, uint32_t a2, uint32_t a3,
                     uint32_t b0, uint32_t b1) {
    asm volatile(
        "mma.sync.aligned.m16n8k16.row.col.f32.f16.f16.f32 "
        "{%0,%1,%2,%3},{%4,%5,%6,%7},{%8,%9},{%0,%1,%2,%3};\n"
        : "+f"(c[0]), "+f"(c[1]), "+f"(c[2]), "+f"(c[3])
        : "r"(a0), "r"(a1), "r"(a2), "r"(a3), "r"(b0), "r"(b1));
}
DEVINL void cpasync16(uint32_t sdst, const void* gsrc) {
    asm volatile("cp.async.cg.shared.global [%0], [%1], 16;\n"
                 :: "r"(sdst), "l"(gsrc));
}
DEVINL void cpcommit() { asm volatile("cp.async.commit_group;\n" ::: "memory"); }
template <int N> DEVINL void cpwait() {
    asm volatile("cp.async.wait_group %0;\n" :: "n"(N) : "memory");
}

// ---------------- TN GEMM -----------------------------------------------------
// C[z][m][n] = scale * sum_k A[z][m][k] * Bt[z][n][k]  (+ bias)
// CTA tile 128(M) x 256(N), BK=32, 3 stages, 256 threads, warp tile 64x64.
static constexpr int BM = 128, BN = 256, BK = 32, STG = 3;
static constexpr int LDS_ROW = BK + 8;                       // 40 halves, 80 B
static constexpr int A_STAGE = BM * LDS_ROW;                 // halves
static constexpr int B_STAGE = BN * LDS_ROW;
static constexpr int SMEM_SZ = (STG * (A_STAGE + B_STAGE)) * 2 + 256;

template <bool OUT_HALF>
__launch_bounds__(256, 1)
__global__ void gemm_tn(const __half* __restrict__ A, const __half* __restrict__ Bt,
                        void* __restrict__ Cv, int K, int lda, int ldb, int ldc,
                        long sAz, long sBz, long sCz,
                        const float* __restrict__ bias, int biasStrideZ, float scale) {
    extern __shared__ __half sm[];
    const int z = blockIdx.z;
    A += (long)z * sAz;
    Bt += (long)z * sBz;
    const int n0 = blockIdx.x * BN, m0 = blockIdx.y * BM;
    const int tid = threadIdx.x, lane = tid & 31, warp = tid >> 5;
    const int wm = (warp & 1) * 64, wn = (warp >> 1) * 64;   // 2x4 warp grid

    __half* Asm = sm;                       // [STG][BM][LDS_ROW]
    __half* Bsm = sm + STG * A_STAGE;       // [STG][BN][LDS_ROW]

    // A: 128 rows * 4 chunks(8 halves) = 512 chunks, 2/thread
    // B: 256 rows * 4 chunks = 1024 chunks, 4/thread
    auto load_tile = [&](int kt, int st) {
        const __half* Ab = A + (long)m0 * lda + kt * BK;
        uint32_t abase = smem_u32(Asm + st * A_STAGE);
#pragma unroll
        for (int j = 0; j < 2; j++) {
            int ci = tid + j * 256, r = ci >> 2, kc = (ci & 3) * 8;
            cpasync16(abase + (r * LDS_ROW + kc) * 2, Ab + (long)r * lda + kc);
        }
        const __half* Bb = Bt + (long)n0 * ldb + kt * BK;
        uint32_t bbase = smem_u32(Bsm + st * B_STAGE);
#pragma unroll
        for (int j = 0; j < 4; j++) {
            int ci = tid + j * 256, r = ci >> 2, kc = (ci & 3) * 8;
            cpasync16(bbase + (r * LDS_ROW + kc) * 2, Bb + (long)r * ldb + kc);
        }
        cpcommit();
    };

    float c[4][8][4];
#pragma unroll
    for (int mt = 0; mt < 4; mt++)
#pragma unroll
        for (int nt = 0; nt < 8; nt++)
#pragma unroll
            for (int i = 0; i < 4; i++) c[mt][nt][i] = 0.f;

    const int T = K / BK;
    load_tile(0, 0);
    load_tile(1, 1);

    for (int kt = 0; kt < T; kt++) {
        if (kt + 1 < T) cpwait<1>(); else cpwait<0>();
        __syncthreads();   // tile kt resident; compute(kt-1) done by ALL threads
        if (kt + 2 < T) load_tile(kt + 2, (kt + 2) % STG);   // overwrites stage of kt-1

        const __half* As = Asm + (kt % STG) * A_STAGE;
        const __half* Bs = Bsm + (kt % STG) * B_STAGE;
#pragma unroll
        for (int kk = 0; kk < 2; kk++) {
            uint32_t a[4][4];
#pragma unroll
            for (int mt = 0; mt < 4; mt++) {
                uint32_t addr = smem_u32(
                    As + (wm + mt * 16 + (lane & 15)) * LDS_ROW + kk * 16 + (lane >> 4) * 8);
                ldm_x4(a[mt][0], a[mt][1], a[mt][2], a[mt][3], addr);
            }
            uint32_t b[8][2];
#pragma unroll
            for (int nt = 0; nt < 8; nt++) {
                uint32_t addr = smem_u32(
                    Bs + (wn + nt * 8 + (lane & 7)) * LDS_ROW + kk * 16 + ((lane >> 3) & 1) * 8);
                ldm_x2(b[nt][0], b[nt][1], addr);
            }
#pragma unroll
            for (int mt = 0; mt < 4; mt++)
#pragma unroll
                for (int nt = 0; nt < 8; nt++)
                    mma16816(c[mt][nt], a[mt][0], a[mt][1], a[mt][2], a[mt][3],
                             b[nt][0], b[nt][1]);
        }
    }

    // ---- epilogue ----
    const int g = lane >> 2, t4 = lane & 3;
#pragma unroll
    for (int mt = 0; mt < 4; mt++) {
#pragma unroll
        for (int nt = 0; nt < 8; nt++) {
            int col = n0 + wn + nt * 8 + t4 * 2;
            float b0 = 0.f, b1 = 0.f;
            if (bias) {
                b0 = bias[z * biasStrideZ + col];
                b1 = bias[z * biasStrideZ + col + 1];
            }
#pragma unroll
            for (int h = 0; h < 2; h++) {
                int row = m0 + wm + mt * 16 + g + h * 8;
                float v0 = c[mt][nt][h * 2 + 0] * scale + b0;
                float v1 = c[mt][nt][h * 2 + 1] * scale + b1;
                long off = (long)z * sCz + (long)row * ldc + col;
                if (OUT_HALF) {
                    *(__half2*)((__half*)Cv + off) = __floats2half2_rn(v0, v1);
                } else {
                    *(float2*)((float*)Cv + off) = make_float2(v0, v1);
                }
            }
        }
    }
}

// ---------------- small kernels ----------------------------------------------
__global__ void f2h2_kernel(const float2* __restrict__ x, __half2* __restrict__ y, int n2) {
    int i = blockIdx.x * blockDim.x + threadIdx.x;
    int stride = gridDim.x * blockDim.x;
    for (; i < n2; i += stride) {
        float2 v = x[i];
        y[i] = __floats2half2_rn(v.x, v.y);
    }
}

// W [k][n] f32 -> Wt [n][k] half (transpose + convert)
__global__ void f2ht_kernel(const float* __restrict__ W, __half* __restrict__ Wt) {
    __shared__ float t[32][33];
    const int k0 = blockIdx.x * 32, n0 = blockIdx.y * 32;
    const int tx = threadIdx.x, ty = threadIdx.y;   // (32, 8)
#pragma unroll
    for (int i = 0; i < 4; i++) {
        int r = ty + i * 8;
        t[r][tx] = W[(long)(k0 + r) * D + n0 + tx];
    }
    __syncthreads();
#pragma unroll
    for (int i = 0; i < 4; i++) {
        int r = ty + i * 8;
        Wt[(long)(n0 + r) * D + k0 + tx] = __float2half(t[tx][r]);
    }
}

// vconst[b][n] = X1[b] @ Wv[:D][.,n] + bv[n]
__global__ void vconst_kernel(const float* __restrict__ X1, const float* __restrict__ Wv,
                              const float* __restrict__ bv, float* __restrict__ vc) {
    int n = blockIdx.x * blockDim.x + threadIdx.x;
    int b = blockIdx.y;
    float acc = bv[n];
    const float* x = X1 + b * D;
    for (int k = 0; k < D; k++) acc += x[k] * Wv[(long)k * D + n];
    vc[b * D + n] = acc;
}

// corr[b][d] = -(alpha/S) * sum_s Vh[b][s][d]
__global__ void corr_kernel(const __half* __restrict__ Vh, const float* __restrict__ alpha,
                            float* __restrict__ corr) {
    int d = blockIdx.x * blockDim.x + threadIdx.x;
    int b = blockIdx.y;
    float s = 0.f;
    const __half* v = Vh + (long)b * S * D + d;
    for (int i = 0; i < S; i++) s += __half2float(v[(long)i * D]);
    corr[b * D + d] = -(*alpha) * (1.0f / (float)S) * s;
}

// Vh [s][d] -> VhT [d][s]
__global__ void transposeV_kernel(const __half* __restrict__ Vh, __half* __restrict__ VhT) {
    __shared__ __half t[64][64 + 8];
    const int z = blockIdx.z;
    const int s0 = blockIdx.x * 64, d0 = blockIdx.y * 64;
    const __half* src = Vh + (long)z * S * D;
    __half* dst = VhT + (long)z * S * D;
    const int tid = threadIdx.x;
#pragma unroll
    for (int j = 0; j < 16; j++) {
        int e = j * 256 + tid, r = e >> 6, c = e & 63;
        t[r][c] = src[(long)(s0 + r) * D + d0 + c];
    }
    __syncthreads();
#pragma unroll
    for (int j = 0; j < 16; j++) {
        int e = j * 256 + tid, r = e >> 6, c = e & 63;
        dst[(long)(d0 + r) * S + s0 + c] = t[c][r];
    }
}

// in-place row softmax over 2048 half logits
__global__ void softmax_kernel(__half* __restrict__ P) {
    __half* p = P + blockIdx.x * (long)S;
    const int tid = threadIdx.x;

    float v[8];
    float mx = -1e30f;
#pragma unroll
    for (int i = 0; i < 8; i++) {
        v[i] = __half2float(p[tid + i * 256]);
        mx = fmaxf(mx, v[i]);
    }
#pragma unroll
    for (int o = 16; o; o >>= 1) mx = fmaxf(mx, __shfl_xor_sync(0xffffffffu, mx, o));
    __shared__ float redm[8];
    if ((tid & 31) == 0) redm[tid >> 5] = mx;
    __syncthreads();
    float m2 = redm[0];
#pragma unroll
    for (int i = 1; i < 8; i++) m2 = fmaxf(m2, redm[i]);

    float s = 0.f;
#pragma unroll
    for (int i = 0; i < 8; i++) { v[i] = __expf(v[i] - m2); s += v[i]; }
#pragma unroll
    for (int o = 16; o; o >>= 1) s += __shfl_xor_sync(0xffffffffu, s, o);
    __shared__ float reds[8];
    if ((tid & 31) == 0) reds[tid >> 5] = s;
    __syncthreads();
    float st = 0.f;
#pragma unroll
    for (int i = 0; i < 8; i++) st += reds[i];
    float inv = 1.0f / st;
#pragma unroll
    for (int i = 0; i < 8; i++) p[tid + i * 256] = __float2half(v[i] * inv);
}

// ---------------- launch ------------------------------------------------------
extern "C" void kernel_launch(void* const* d_in, const int* in_sizes, int n_in,
                              void* d_out, int out_size) {
    const float* X1 = (const float*)d_in[0];
    const float* X2 = (const float*)d_in[1];
    // d_in[2],[3],[6],[7] (Wq1,bq1,Wk1,bk1) are provably dead
    const float* Wq2 = (const float*)d_in[4];
    const float* bq2 = (const float*)d_in[5];
    const float* Wk2 = (const float*)d_in[8];
    const float* bk2 = (const float*)d_in[9];
    const float* Wv = (const float*)d_in[10];
    const float* bv = (const float*)d_in[11];
    const float* alpha = (const float*)d_in[12];
    float* out = (float*)d_out;

    __half *Xh, *Wt, *Qh, *Kh, *Vh, *VhT, *P;
    float *vconst, *corr;
    cudaGetSymbolAddress((void**)&Xh, g_Xh);
    cudaGetSymbolAddress((void**)&Wt, g_Wt);
    cudaGetSymbolAddress((void**)&Qh, g_Qh);
    cudaGetSymbolAddress((void**)&Kh, g_Kh);
    cudaGetSymbolAddress((void**)&Vh, g_Vh);
    cudaGetSymbolAddress((void**)&VhT, g_VhT);
    cudaGetSymbolAddress((void**)&P, g_P);
    cudaGetSymbolAddress((void**)&vconst, g_vconst);
    cudaGetSymbolAddress((void**)&corr, g_corr);

    cudaFuncSetAttribute(gemm_tn<true>, cudaFuncAttributeMaxDynamicSharedMemorySize, SMEM_SZ);
    cudaFuncSetAttribute(gemm_tn<false>, cudaFuncAttributeMaxDynamicSharedMemorySize, SMEM_SZ);

    const int NX = B * S * D;
    const int NW = D * D;

    // 1. conversions (+ weight transposes) + vconst
    f2h2_kernel<<<4096, 256>>>((const float2*)X2, (__half2*)Xh, NX / 2);
    {
        dim3 bl(32, 8), gr(32, 32);
        f2ht_kernel<<<gr, bl>>>(Wq2, Wt + 0 * NW);
        f2ht_kernel<<<gr, bl>>>(Wk2, Wt + 1 * NW);
        f2ht_kernel<<<gr, bl>>>(Wv + (long)D * D, Wt + 2 * NW);   // bottom rows
    }
    vconst_kernel<<<dim3(4, B), 256>>>(X1, Wv, bv, vconst);

    // 2. Q/K/V projections: [z][2048][1024] = Xh[z] @ Wt^T (+bias)
    {
        dim3 grid(D / BN, S / BM, B);
        gemm_tn<true><<<grid, 256, SMEM_SZ>>>(Xh, Wt + 0 * NW, Qh, D, D, D, D,
                                              (long)S * D, 0, (long)S * D, bq2, 0, 1.0f);
        gemm_tn<true><<<grid, 256, SMEM_SZ>>>(Xh, Wt + 1 * NW, Kh, D, D, D, D,
                                              (long)S * D, 0, (long)S * D, bk2, 0, 1.0f);
        gemm_tn<true><<<grid, 256, SMEM_SZ>>>(Xh, Wt + 2 * NW, Vh, D, D, D, D,
                                              (long)S * D, 0, (long)S * D, vconst, D, 1.0f);
    }

    // 3. correction + V transpose
    corr_kernel<<<dim3(4, B), 256>>>(Vh, alpha, corr);
    transposeV_kernel<<<dim3(S / 64, D / 64, B), 256>>>(Vh, VhT);

    // 4. logits[z][s][s'] = (Qh @ Kh^T)/32 -> g_P as half
    {
        dim3 grid(S / BN, S / BM, B);
        gemm_tn<true><<<grid, 256, SMEM_SZ>>>(Qh, Kh, P, D, D, D, S,
                                              (long)S * D, (long)S * D, (long)S * S,
                                              nullptr, 0, 0.03125f);
    }

    // 5. in-place softmax rows of g_P
    softmax_kernel<<<B * S, 256>>>(P);

    // 6. out[z][s][d] = P[z] @ V[z] + corr[z]
    {
        dim3 grid(D / BN, S / BM, B);
        gemm_tn<false><<<grid, 256, SMEM_SZ>>>(P, VhT, out, S, S, S, D,
                                               (long)S * S, (long)S * D, (long)S * D,
                                               corr, D, 1.0f);
    }
}

// round 11
// speedup vs baseline: 1.9094x; 1.9094x over previous
#include <cuda_runtime.h>
#include <cuda_fp16.h>
#include <cstdint>

// ----------------------------------------------------------------------------
// diff_attention: B=8, S=2048, D=1024 — HMMA (mma.sync), occupancy-safe.
// R10 lesson: 64x64 warp tiles -> ~200 regs -> 1 CTA/SM -> 1714us (REGRESSION).
// This kernel: round-2's proven 32x64 warp tile / 2 CTAs per SM geometry,
// with BK=64 (4x fewer barriers), single __syncthreads per k-tile,
// uniform TN layout, fp16 in-place logits.
//
// Math simplifications (proved from the reference):
//  * softmax(A1) == 1/S exactly -> out = softmax(A2) @ V - (alpha/S)*colsum(V)
//  * V = vconst[b] + X2 @ Wv[D:],  vconst[b] = X1[b] @ Wv[:D] + bv
// ----------------------------------------------------------------------------

#define DEVINL __device__ __forceinline__

static constexpr int B = 8;
static constexpr int S = 2048;
static constexpr int D = 1024;

// ---------------- device scratch ---------------------------------------------
__device__ __half g_Xh[B * S * D];            // 32 MB
__device__ __half g_Wt[3 * D * D];            //  6 MB  W^T [n][k]: Wq2,Wk2,Wv_bot
__device__ __half g_Qh[B * S * D];            // 32 MB
__device__ __half g_Kh[B * S * D];            // 32 MB
__device__ __half g_Vh[B * S * D];            // 32 MB  V [s][d]
__device__ __half g_VhT[B * S * D];           // 32 MB  V^T [d][s]
__device__ float  g_vconst[B * D];
__device__ float  g_corr[B * D];
__device__ __half g_P[(long)B * S * S];       // 64 MB: logits then probs (in-place)

// ---------------- PTX helpers -------------------------------------------------
DEVINL uint32_t smem_u32(const void* p) {
    return (uint32_t)__cvta_generic_to_shared(p);
}
DEVINL void ldm_x4(uint32_t& r0, uint32_t& r1, uint32_t& r2, uint32_t& r3, uint32_t a) {
    asm volatile("ldmatrix.sync.aligned.m8n8.x4.shared.b16 {%0,%1,%2,%3},[%4];\n"
                 : "=r"(r0), "=r"(r1), "=r"(r2), "=r"(r3) : "r"(a));
}
DEVINL void ldm_x2(uint32_t& r0, uint32_t& r1, uint32_t a) {
    asm volatile("ldmatrix.sync.aligned.m8n8.x2.shared.b16 {%0,%1},[%2];\n"
                 : "=r"(r0), "=r"(r1) : "r"(a));
}
DEVINL void mma16816(float c[4], uint32_t a0, uint32_t a1, uint32_t a2, uint32_t a3,
                     uint32_t b0, uint32_t b1) {
    asm volatile(
        "mma.sync.aligned.m16n8k16.row.col.f32.f16.f16.f32 "
        "{%0,%1,%2,%3},{%4,%5,%6,%7},{%8,%9},{%0,%1,%2,%3};\n"
        : "+f"(c[0]), "+f"(c[1]), "+f"(c[2]), "+f"(c[3])
        : "r"(a0), "r"(a1), "r"(a2), "r"(a3), "r"(b0), "r"(b1));
}
DEVINL void cpasync16(uint32_t sdst, const void* gsrc) {
    asm volatile("cp.async.cg.shared.global [%0], [%1], 16;\n"
                 :: "r"(sdst), "l"(gsrc));
}
DEVINL void cpcommit() { asm volatile("cp.async.commit_group;\n" ::: "memory"); }
template <int N> DEVINL void cpwait() {
    asm volatile("cp.async.wait_group %0;\n" :: "n"(N) : "memory");
}

// ---------------- TN GEMM -----------------------------------------------------
// C[z][m][n] = scale * sum_k A[z][m][k] * Bt[z][n][k]  (+ bias)
// CTA tile 128x128, BK=64, 2 stages, 256 threads, warp tile 32x64 (4x2 warps).
// ~120 regs/thread -> 2 CTAs/SM (forced by __launch_bounds__(256,2)).
static constexpr int BM = 128, BN = 128, BK = 64, STG = 2;
static constexpr int LDS_ROW = BK + 8;                       // 72 halves, 144 B
static constexpr int A_STAGE = BM * LDS_ROW;                 // halves
static constexpr int B_STAGE = BN * LDS_ROW;
static constexpr int SMEM_SZ = (STG * (A_STAGE + B_STAGE)) * 2 + 256;  // ~74 KB

template <bool OUT_HALF>
__launch_bounds__(256, 2)
__global__ void gemm_tn(const __half* __restrict__ A, const __half* __restrict__ Bt,
                        void* __restrict__ Cv, int K, int lda, int ldb, int ldc,
                        long sAz, long sBz, long sCz,
                        const float* __restrict__ bias, int biasStrideZ, float scale) {
    extern __shared__ __half sm[];
    const int z = blockIdx.z;
    A += (long)z * sAz;
    Bt += (long)z * sBz;
    const int n0 = blockIdx.x * BN, m0 = blockIdx.y * BM;
    const int tid = threadIdx.x, lane = tid & 31, warp = tid >> 5;
    const int wm = (warp & 3) * 32, wn = (warp >> 2) * 64;   // 4x2 warp grid

    __half* Asm = sm;                       // [STG][BM][LDS_ROW]
    __half* Bsm = sm + STG * A_STAGE;       // [STG][BN][LDS_ROW]

    // A: 128 rows * 8 chunks(8 halves) = 1024 chunks, 4/thread; B identical.
    auto load_tile = [&](int kt, int st) {
        const __half* Ab = A + (long)m0 * lda + kt * BK;
        uint32_t abase = smem_u32(Asm + st * A_STAGE);
#pragma unroll
        for (int j = 0; j < 4; j++) {
            int ci = tid + j * 256, r = ci >> 3, kc = (ci & 7) * 8;
            cpasync16(abase + (r * LDS_ROW + kc) * 2, Ab + (long)r * lda + kc);
        }
        const __half* Bb = Bt + (long)n0 * ldb + kt * BK;
        uint32_t bbase = smem_u32(Bsm + st * B_STAGE);
#pragma unroll
        for (int j = 0; j < 4; j++) {
            int ci = tid + j * 256, r = ci >> 3, kc = (ci & 7) * 8;
            cpasync16(bbase + (r * LDS_ROW + kc) * 2, Bb + (long)r * ldb + kc);
        }
        cpcommit();
    };

    float c[2][8][4];
#pragma unroll
    for (int mt = 0; mt < 2; mt++)
#pragma unroll
        for (int nt = 0; nt < 8; nt++)
#pragma unroll
            for (int i = 0; i < 4; i++) c[mt][nt][i] = 0.f;

    const int T = K / BK;
    load_tile(0, 0);

    for (int kt = 0; kt < T; kt++) {
        cpwait<0>();        // own groups done (tile kt among them)
        __syncthreads();    // all threads' loads visible; compute(kt-1) finished
        if (kt + 1 < T) load_tile(kt + 1, (kt + 1) & 1);   // overlaps compute(kt)

        const __half* As = Asm + (kt & 1) * A_STAGE;
        const __half* Bs = Bsm + (kt & 1) * B_STAGE;
#pragma unroll
        for (int kk = 0; kk < 4; kk++) {
            uint32_t a[2][4];
#pragma unroll
            for (int mt = 0; mt < 2; mt++) {
                uint32_t addr = smem_u32(
                    As + (wm + mt * 16 + (lane & 15)) * LDS_ROW + kk * 16 + (lane >> 4) * 8);
                ldm_x4(a[mt][0], a[mt][1], a[mt][2], a[mt][3], addr);
            }
            uint32_t b[8][2];
#pragma unroll
            for (int nt = 0; nt < 8; nt++) {
                uint32_t addr = smem_u32(
                    Bs + (wn + nt * 8 + (lane & 7)) * LDS_ROW + kk * 16 + ((lane >> 3) & 1) * 8);
                ldm_x2(b[nt][0], b[nt][1], addr);
            }
#pragma unroll
            for (int mt = 0; mt < 2; mt++)
#pragma unroll
                for (int nt = 0; nt < 8; nt++)
                    mma16816(c[mt][nt], a[mt][0], a[mt][1], a[mt][2], a[mt][3],
                             b[nt][0], b[nt][1]);
        }
    }

    // ---- epilogue ----
    const int g = lane >> 2, t4 = lane & 3;
#pragma unroll
    for (int mt = 0; mt < 2; mt++) {
#pragma unroll
        for (int nt = 0; nt < 8; nt++) {
            int col = n0 + wn + nt * 8 + t4 * 2;
            float b0 = 0.f, b1 = 0.f;
            if (bias) {
                b0 = bias[z * biasStrideZ + col];
                b1 = bias[z * biasStrideZ + col + 1];
            }
#pragma unroll
            for (int h = 0; h < 2; h++) {
                int row = m0 + wm + mt * 16 + g + h * 8;
                float v0 = c[mt][nt][h * 2 + 0] * scale + b0;
                float v1 = c[mt][nt][h * 2 + 1] * scale + b1;
                long off = (long)z * sCz + (long)row * ldc + col;
                if (OUT_HALF) {
                    *(__half2*)((__half*)Cv + off) = __floats2half2_rn(v0, v1);
                } else {
                    *(float2*)((float*)Cv + off) = make_float2(v0, v1);
                }
            }
        }
    }
}

// ---------------- small kernels ----------------------------------------------
__global__ void f2h2_kernel(const float2* __restrict__ x, __half2* __restrict__ y, int n2) {
    int i = blockIdx.x * blockDim.x + threadIdx.x;
    int stride = gridDim.x * blockDim.x;
    for (; i < n2; i += stride) {
        float2 v = x[i];
        y[i] = __floats2half2_rn(v.x, v.y);
    }
}

// W [k][n] f32 -> Wt [n][k] half (transpose + convert)
__global__ void f2ht_kernel(const float* __restrict__ W, __half* __restrict__ Wt) {
    __shared__ float t[32][33];
    const int k0 = blockIdx.x * 32, n0 = blockIdx.y * 32;
    const int tx = threadIdx.x, ty = threadIdx.y;   // (32, 8)
#pragma unroll
    for (int i = 0; i < 4; i++) {
        int r = ty + i * 8;
        t[r][tx] = W[(long)(k0 + r) * D + n0 + tx];
    }
    __syncthreads();
#pragma unroll
    for (int i = 0; i < 4; i++) {
        int r = ty + i * 8;
        Wt[(long)(n0 + r) * D + k0 + tx] = __float2half(t[tx][r]);
    }
}

// vconst[b][n] = X1[b] @ Wv[:D][.,n] + bv[n]
__global__ void vconst_kernel(const float* __restrict__ X1, const float* __restrict__ Wv,
                              const float* __restrict__ bv, float* __restrict__ vc) {
    int n = blockIdx.x * blockDim.x + threadIdx.x;
    int b = blockIdx.y;
    float acc = bv[n];
    const float* x = X1 + b * D;
    for (int k = 0; k < D; k++) acc += x[k] * Wv[(long)k * D + n];
    vc[b * D + n] = acc;
}

// corr[b][d] = -(alpha/S) * sum_s Vh[b][s][d]
__global__ void corr_kernel(const __half* __restrict__ Vh, const float* __restrict__ alpha,
                            float* __restrict__ corr) {
    int d = blockIdx.x * blockDim.x + threadIdx.x;
    int b = blockIdx.y;
    float s = 0.f;
    const __half* v = Vh + (long)b * S * D + d;
    for (int i = 0; i < S; i++) s += __half2float(v[(long)i * D]);
    corr[b * D + d] = -(*alpha) * (1.0f / (float)S) * s;
}

// Vh [s][d] -> VhT [d][s]
__global__ void transposeV_kernel(const __half* __restrict__ Vh, __half* __restrict__ VhT) {
    __shared__ __half t[64][64 + 8];
    const int z = blockIdx.z;
    const int s0 = blockIdx.x * 64, d0 = blockIdx.y * 64;
    const __half* src = Vh + (long)z * S * D;
    __half* dst = VhT + (long)z * S * D;
    const int tid = threadIdx.x;
#pragma unroll
    for (int j = 0; j < 16; j++) {
        int e = j * 256 + tid, r = e >> 6, c = e & 63;
        t[r][c] = src[(long)(s0 + r) * D + d0 + c];
    }
    __syncthreads();
#pragma unroll
    for (int j = 0; j < 16; j++) {
        int e = j * 256 + tid, r = e >> 6, c = e & 63;
        dst[(long)(d0 + r) * S + s0 + c] = t[c][r];
    }
}

// in-place row softmax over 2048 half logits
__global__ void softmax_kernel(__half* __restrict__ P) {
    __half* p = P + blockIdx.x * (long)S;
    const int tid = threadIdx.x;

    float v[8];
    float mx = -1e30f;
#pragma unroll
    for (int i = 0; i < 8; i++) {
        v[i] = __half2float(p[tid + i * 256]);
        mx = fmaxf(mx, v[i]);
    }
#pragma unroll
    for (int o = 16; o; o >>= 1) mx = fmaxf(mx, __shfl_xor_sync(0xffffffffu, mx, o));
    __shared__ float redm[8];
    if ((tid & 31) == 0) redm[tid >> 5] = mx;
    __syncthreads();
    float m2 = redm[0];
#pragma unroll
    for (int i = 1; i < 8; i++) m2 = fmaxf(m2, redm[i]);

    float s = 0.f;
#pragma unroll
    for (int i = 0; i < 8; i++) { v[i] = __expf(v[i] - m2); s += v[i]; }
#pragma unroll
    for (int o = 16; o; o >>= 1) s += __shfl_xor_sync(0xffffffffu, s, o);
    __shared__ float reds[8];
    if ((tid & 31) == 0) reds[tid >> 5] = s;
    __syncthreads();
    float st = 0.f;
#pragma unroll
    for (int i = 0; i < 8; i++) st += reds[i];
    float inv = 1.0f / st;
#pragma unroll
    for (int i = 0; i < 8; i++) p[tid + i * 256] = __float2half(v[i] * inv);
}

// ---------------- launch ------------------------------------------------------
extern "C" void kernel_launch(void* const* d_in, const int* in_sizes, int n_in,
                              void* d_out, int out_size) {
    const float* X1 = (const float*)d_in[0];
    const float* X2 = (const float*)d_in[1];
    // d_in[2],[3],[6],[7] (Wq1,bq1,Wk1,bk1) are provably dead
    const float* Wq2 = (const float*)d_in[4];
    const float* bq2 = (const float*)d_in[5];
    const float* Wk2 = (const float*)d_in[8];
    const float* bk2 = (const float*)d_in[9];
    const float* Wv = (const float*)d_in[10];
    const float* bv = (const float*)d_in[11];
    const float* alpha = (const float*)d_in[12];
    float* out = (float*)d_out;

    __half *Xh, *Wt, *Qh, *Kh, *Vh, *VhT, *P;
    float *vconst, *corr;
    cudaGetSymbolAddress((void**)&Xh, g_Xh);
    cudaGetSymbolAddress((void**)&Wt, g_Wt);
    cudaGetSymbolAddress((void**)&Qh, g_Qh);
    cudaGetSymbolAddress((void**)&Kh, g_Kh);
    cudaGetSymbolAddress((void**)&Vh, g_Vh);
    cudaGetSymbolAddress((void**)&VhT, g_VhT);
    cudaGetSymbolAddress((void**)&P, g_P);
    cudaGetSymbolAddress((void**)&vconst, g_vconst);
    cudaGetSymbolAddress((void**)&corr, g_corr);

    cudaFuncSetAttribute(gemm_tn<true>, cudaFuncAttributeMaxDynamicSharedMemorySize, SMEM_SZ);
    cudaFuncSetAttribute(gemm_tn<false>, cudaFuncAttributeMaxDynamicSharedMemorySize, SMEM_SZ);

    const int NX = B * S * D;
    const int NW = D * D;

    // 1. conversions (+ weight transposes) + vconst
    f2h2_kernel<<<4096, 256>>>((const float2*)X2, (__half2*)Xh, NX / 2);
    {
        dim3 bl(32, 8), gr(32, 32);
        f2ht_kernel<<<gr, bl>>>(Wq2, Wt + 0 * NW);
        f2ht_kernel<<<gr, bl>>>(Wk2, Wt + 1 * NW);
        f2ht_kernel<<<gr, bl>>>(Wv + (long)D * D, Wt + 2 * NW);   // bottom rows
    }
    vconst_kernel<<<dim3(4, B), 256>>>(X1, Wv, bv, vconst);

    // 2. Q/K/V projections: [z][2048][1024] = Xh[z] @ Wt^T (+bias)
    {
        dim3 grid(D / BN, S / BM, B);
        gemm_tn<true><<<grid, 256, SMEM_SZ>>>(Xh, Wt + 0 * NW, Qh, D, D, D, D,
                                              (long)S * D, 0, (long)S * D, bq2, 0, 1.0f);
        gemm_tn<true><<<grid, 256, SMEM_SZ>>>(Xh, Wt + 1 * NW, Kh, D, D, D, D,
                                              (long)S * D, 0, (long)S * D, bk2, 0, 1.0f);
        gemm_tn<true><<<grid, 256, SMEM_SZ>>>(Xh, Wt + 2 * NW, Vh, D, D, D, D,
                                              (long)S * D, 0, (long)S * D, vconst, D, 1.0f);
    }

    // 3. correction + V transpose
    corr_kernel<<<dim3(4, B), 256>>>(Vh, alpha, corr);
    transposeV_kernel<<<dim3(S / 64, D / 64, B), 256>>>(Vh, VhT);

    // 4. logits[z][s][s'] = (Qh @ Kh^T)/32 -> g_P as half
    {
        dim3 grid(S / BN, S / BM, B);
        gemm_tn<true><<<grid, 256, SMEM_SZ>>>(Qh, Kh, P, D, D, D, S,
                                              (long)S * D, (long)S * D, (long)S * S,
                                              nullptr, 0, 0.03125f);
    }

    // 5. in-place softmax rows of g_P
    softmax_kernel<<<B * S, 256>>>(P);

    // 6. out[z][s][d] = P[z] @ V[z] + corr[z]
    {
        dim3 grid(D / BN, S / BM, B);
        gemm_tn<false><<<grid, 256, SMEM_SZ>>>(P, VhT, out, S, S, S, D,
                                               (long)S * S, (long)S * D, (long)S * D,
                                               corr, D, 1.0f);
    }
}

// round 12
// speedup vs baseline: 1.9418x; 1.0170x over previous
#include <cuda_runtime.h>
#include <cuda_fp16.h>
#include <cstdint>

// ----------------------------------------------------------------------------
// diff_attention: B=8, S=2048, D=1024 — HMMA (mma.sync), occupancy-safe.
// Proven geometry (R11, 897.8us): CTA 128x128, warp 32x64, BK=64, 2 CTAs/SM,
// single __syncthreads per k-tile, fp16 in-place logits.
// R12 deltas: (1) fused QKV projection (one GEMM, N=3072, packed [z][s][3D]
// output) to kill wave-quantization tails; (2) B-fragments via ldmatrix.x4
// (two n-tiles per instruction) to cut LDSM issue 40%.
//
// Math simplifications (proved from the reference):
//  * softmax(A1) == 1/S exactly -> out = softmax(A2) @ V - (alpha/S)*colsum(V)
//  * V = vconst[b] + X2 @ Wv[D:],  vconst[b] = X1[b] @ Wv[:D] + bv
// ----------------------------------------------------------------------------

#define DEVINL __device__ __forceinline__

static constexpr int B = 8;
static constexpr int S = 2048;
static constexpr int D = 1024;
static constexpr int D3 = 3 * D;

// ---------------- device scratch ---------------------------------------------
__device__ __half g_Xh[B * S * D];            // 32 MB
__device__ __half g_Wt[3 * D * D];            //  6 MB  W^T [n][k]: Wq2 | Wk2 | Wv_bot
__device__ __half g_QKV[(long)B * S * D3];    // 96 MB  packed [z][s][3D]: Q|K|V
__device__ __half g_VhT[B * S * D];           // 32 MB  V^T [d][s]
__device__ float  g_vconst[B * D];
__device__ float  g_bias3[B * D3];            // per-z merged bias: bq2|bk2|vconst[z]
__device__ float  g_corr[B * D];
__device__ __half g_P[(long)B * S * S];       // 64 MB: logits then probs (in-place)

// ---------------- PTX helpers -------------------------------------------------
DEVINL uint32_t smem_u32(const void* p) {
    return (uint32_t)__cvta_generic_to_shared(p);
}
DEVINL void ldm_x4(uint32_t& r0, uint32_t& r1, uint32_t& r2, uint32_t& r3, uint32_t a) {
    asm volatile("ldmatrix.sync.aligned.m8n8.x4.shared.b16 {%0,%1,%2,%3},[%4];\n"
                 : "=r"(r0), "=r"(r1), "=r"(r2), "=r"(r3) : "r"(a));
}
DEVINL void mma16816(float c[4], uint32_t a0, uint32_t a1, uint32_t a2, uint32_t a3,
                     uint32_t b0, uint32_t b1) {
    asm volatile(
        "mma.sync.aligned.m16n8k16.row.col.f32.f16.f16.f32 "
        "{%0,%1,%2,%3},{%4,%5,%6,%7},{%8,%9},{%0,%1,%2,%3};\n"
        : "+f"(c[0]), "+f"(c[1]), "+f"(c[2]), "+f"(c[3])
        : "r"(a0), "r"(a1), "r"(a2), "r"(a3), "r"(b0), "r"(b1));
}
DEVINL void cpasync16(uint32_t sdst, const void* gsrc) {
    asm volatile("cp.async.cg.shared.global [%0], [%1], 16;\n"
                 :: "r"(sdst), "l"(gsrc));
}
DEVINL void cpcommit() { asm volatile("cp.async.commit_group;\n" ::: "memory"); }
template <int N> DEVINL void cpwait() {
    asm volatile("cp.async.wait_group %0;\n" :: "n"(N) : "memory");
}

// ---------------- TN GEMM -----------------------------------------------------
// C[z][m][n] = scale * sum_k A[z][m][k] * Bt[z][n][k]  (+ bias)
// CTA tile 128x128, BK=64, 2 stages, 256 threads, warp tile 32x64 (4x2 warps).
static constexpr int BM = 128, BN = 128, BK = 64, STG = 2;
static constexpr int LDS_ROW = BK + 8;                       // 72 halves, 144 B
static constexpr int A_STAGE = BM * LDS_ROW;                 // halves
static constexpr int B_STAGE = BN * LDS_ROW;
static constexpr int SMEM_SZ = (STG * (A_STAGE + B_STAGE)) * 2 + 256;  // ~74 KB

template <bool OUT_HALF>
__launch_bounds__(256, 2)
__global__ void gemm_tn(const __half* __restrict__ A, const __half* __restrict__ Bt,
                        void* __restrict__ Cv, int K, int lda, int ldb, int ldc,
                        long sAz, long sBz, long sCz,
                        const float* __restrict__ bias, int biasStrideZ, float scale) {
    extern __shared__ __half sm[];
    const int z = blockIdx.z;
    A += (long)z * sAz;
    Bt += (long)z * sBz;
    const int n0 = blockIdx.x * BN, m0 = blockIdx.y * BM;
    const int tid = threadIdx.x, lane = tid & 31, warp = tid >> 5;
    const int wm = (warp & 3) * 32, wn = (warp >> 2) * 64;   // 4x2 warp grid

    __half* Asm = sm;                       // [STG][BM][LDS_ROW]
    __half* Bsm = sm + STG * A_STAGE;       // [STG][BN][LDS_ROW]

    auto load_tile = [&](int kt, int st) {
        const __half* Ab = A + (long)m0 * lda + kt * BK;
        uint32_t abase = smem_u32(Asm + st * A_STAGE);
#pragma unroll
        for (int j = 0; j < 4; j++) {
            int ci = tid + j * 256, r = ci >> 3, kc = (ci & 7) * 8;
            cpasync16(abase + (r * LDS_ROW + kc) * 2, Ab + (long)r * lda + kc);
        }
        const __half* Bb = Bt + (long)n0 * ldb + kt * BK;
        uint32_t bbase = smem_u32(Bsm + st * B_STAGE);
#pragma unroll
        for (int j = 0; j < 4; j++) {
            int ci = tid + j * 256, r = ci >> 3, kc = (ci & 7) * 8;
            cpasync16(bbase + (r * LDS_ROW + kc) * 2, Bb + (long)r * ldb + kc);
        }
        cpcommit();
    };

    float c[2][8][4];
#pragma unroll
    for (int mt = 0; mt < 2; mt++)
#pragma unroll
        for (int nt = 0; nt < 8; nt++)
#pragma unroll
            for (int i = 0; i < 4; i++) c[mt][nt][i] = 0.f;

    const int T = K / BK;
    load_tile(0, 0);

    for (int kt = 0; kt < T; kt++) {
        cpwait<0>();        // own groups done (tile kt among them)
        __syncthreads();    // all loads visible; compute(kt-1) finished
        if (kt + 1 < T) load_tile(kt + 1, (kt + 1) & 1);   // overlaps compute(kt)

        const __half* As = Asm + (kt & 1) * A_STAGE;
        const __half* Bs = Bsm + (kt & 1) * B_STAGE;
#pragma unroll
        for (int kk = 0; kk < 4; kk++) {
            uint32_t a[2][4];
#pragma unroll
            for (int mt = 0; mt < 2; mt++) {
                uint32_t addr = smem_u32(
                    As + (wm + mt * 16 + (lane & 15)) * LDS_ROW + kk * 16 + (lane >> 4) * 8);
                ldm_x4(a[mt][0], a[mt][1], a[mt][2], a[mt][3], addr);
            }
            // B: one ldmatrix.x4 covers TWO n-tiles (lanes 16-31 -> second tile)
            uint32_t b[8][2];
#pragma unroll
            for (int ntp = 0; ntp < 4; ntp++) {
                uint32_t addr = smem_u32(
                    Bs + (wn + ntp * 16 + ((lane >> 4) & 1) * 8 + (lane & 7)) * LDS_ROW +
                    kk * 16 + ((lane >> 3) & 1) * 8);
                ldm_x4(b[2 * ntp][0], b[2 * ntp][1], b[2 * ntp + 1][0], b[2 * ntp + 1][1],
                       addr);
            }
#pragma unroll
            for (int mt = 0; mt < 2; mt++)
#pragma unroll
                for (int nt = 0; nt < 8; nt++)
                    mma16816(c[mt][nt], a[mt][0], a[mt][1], a[mt][2], a[mt][3],
                             b[nt][0], b[nt][1]);
        }
    }

    // ---- epilogue ----
    const int g = lane >> 2, t4 = lane & 3;
#pragma unroll
    for (int mt = 0; mt < 2; mt++) {
#pragma unroll
        for (int nt = 0; nt < 8; nt++) {
            int col = n0 + wn + nt * 8 + t4 * 2;
            float b0 = 0.f, b1 = 0.f;
            if (bias) {
                b0 = bias[z * biasStrideZ + col];
                b1 = bias[z * biasStrideZ + col + 1];
            }
#pragma unroll
            for (int h = 0; h < 2; h++) {
                int row = m0 + wm + mt * 16 + g + h * 8;
                float v0 = c[mt][nt][h * 2 + 0] * scale + b0;
                float v1 = c[mt][nt][h * 2 + 1] * scale + b1;
                long off = (long)z * sCz + (long)row * ldc + col;
                if (OUT_HALF) {
                    *(__half2*)((__half*)Cv + off) = __floats2half2_rn(v0, v1);
                } else {
                    *(float2*)((float*)Cv + off) = make_float2(v0, v1);
                }
            }
        }
    }
}

// ---------------- small kernels ----------------------------------------------
__global__ void f2h2_kernel(const float2* __restrict__ x, __half2* __restrict__ y, int n2) {
    int i = blockIdx.x * blockDim.x + threadIdx.x;
    int stride = gridDim.x * blockDim.x;
    for (; i < n2; i += stride) {
        float2 v = x[i];
        y[i] = __floats2half2_rn(v.x, v.y);
    }
}

// W [k][n] f32 -> Wt [n][k] half (transpose + convert)
__global__ void f2ht_kernel(const float* __restrict__ W, __half* __restrict__ Wt) {
    __shared__ float t[32][33];
    const int k0 = blockIdx.x * 32, n0 = blockIdx.y * 32;
    const int tx = threadIdx.x, ty = threadIdx.y;   // (32, 8)
#pragma unroll
    for (int i = 0; i < 4; i++) {
        int r = ty + i * 8;
        t[r][tx] = W[(long)(k0 + r) * D + n0 + tx];
    }
    __syncthreads();
#pragma unroll
    for (int i = 0; i < 4; i++) {
        int r = ty + i * 8;
        Wt[(long)(n0 + r) * D + k0 + tx] = __float2half(t[tx][r]);
    }
}

// vconst[b][n] = X1[b] @ Wv[:D][.,n] + bv[n]
__global__ void vconst_kernel(const float* __restrict__ X1, const float* __restrict__ Wv,
                              const float* __restrict__ bv, float* __restrict__ vc) {
    int n = blockIdx.x * blockDim.x + threadIdx.x;
    int b = blockIdx.y;
    float acc = bv[n];
    const float* x = X1 + b * D;
    for (int k = 0; k < D; k++) acc += x[k] * Wv[(long)k * D + n];
    vc[b * D + n] = acc;
}

// merged bias: g_bias3[z] = [ bq2 | bk2 | vconst[z] ]
__global__ void biasmerge_kernel(const float* __restrict__ bq2,
                                 const float* __restrict__ bk2,
                                 const float* __restrict__ vc,
                                 float* __restrict__ b3) {
    int n = blockIdx.x * blockDim.x + threadIdx.x;   // 0..D3-1
    int z = blockIdx.y;
    float v;
    if (n < D) v = bq2[n];
    else if (n < 2 * D) v = bk2[n - D];
    else v = vc[z * D + (n - 2 * D)];
    b3[z * D3 + n] = v;
}

// corr[b][d] = -(alpha/S) * sum_s V[b][s][d]   (V = QKV + 2D, row stride 3D)
__global__ void corr_kernel(const __half* __restrict__ QKV, const float* __restrict__ alpha,
                            float* __restrict__ corr) {
    int d = blockIdx.x * blockDim.x + threadIdx.x;
    int b = blockIdx.y;
    float s = 0.f;
    const __half* v = QKV + (long)b * S * D3 + 2 * D + d;
    for (int i = 0; i < S; i++) s += __half2float(v[(long)i * D3]);
    corr[b * D + d] = -(*alpha) * (1.0f / (float)S) * s;
}

// V [s][d] (packed, stride 3D) -> VhT [d][s]
__global__ void transposeV_kernel(const __half* __restrict__ QKV, __half* __restrict__ VhT) {
    __shared__ __half t[64][64 + 8];
    const int z = blockIdx.z;
    const int s0 = blockIdx.x * 64, d0 = blockIdx.y * 64;
    const __half* src = QKV + (long)z * S * D3 + 2 * D;
    __half* dst = VhT + (long)z * S * D;
    const int tid = threadIdx.x;
#pragma unroll
    for (int j = 0; j < 16; j++) {
        int e = j * 256 + tid, r = e >> 6, c = e & 63;
        t[r][c] = src[(long)(s0 + r) * D3 + d0 + c];
    }
    __syncthreads();
#pragma unroll
    for (int j = 0; j < 16; j++) {
        int e = j * 256 + tid, r = e >> 6, c = e & 63;
        dst[(long)(d0 + r) * S + s0 + c] = t[c][r];
    }
}

// in-place row softmax over 2048 half logits
__global__ void softmax_kernel(__half* __restrict__ P) {
    __half* p = P + blockIdx.x * (long)S;
    const int tid = threadIdx.x;

    float v[8];
    float mx = -1e30f;
#pragma unroll
    for (int i = 0; i < 8; i++) {
        v[i] = __half2float(p[tid + i * 256]);
        mx = fmaxf(mx, v[i]);
    }
#pragma unroll
    for (int o = 16; o; o >>= 1) mx = fmaxf(mx, __shfl_xor_sync(0xffffffffu, mx, o));
    __shared__ float redm[8];
    if ((tid & 31) == 0) redm[tid >> 5] = mx;
    __syncthreads();
    float m2 = redm[0];
#pragma unroll
    for (int i = 1; i < 8; i++) m2 = fmaxf(m2, redm[i]);

    float s = 0.f;
#pragma unroll
    for (int i = 0; i < 8; i++) { v[i] = __expf(v[i] - m2); s += v[i]; }
#pragma unroll
    for (int o = 16; o; o >>= 1) s += __shfl_xor_sync(0xffffffffu, s, o);
    __shared__ float reds[8];
    if ((tid & 31) == 0) reds[tid >> 5] = s;
    __syncthreads();
    float st = 0.f;
#pragma unroll
    for (int i = 0; i < 8; i++) st += reds[i];
    float inv = 1.0f / st;
#pragma unroll
    for (int i = 0; i < 8; i++) p[tid + i * 256] = __float2half(v[i] * inv);
}

// ---------------- launch ------------------------------------------------------
extern "C" void kernel_launch(void* const* d_in, const int* in_sizes, int n_in,
                              void* d_out, int out_size) {
    const float* X1 = (const float*)d_in[0];
    const float* X2 = (const float*)d_in[1];
    // d_in[2],[3],[6],[7] (Wq1,bq1,Wk1,bk1) are provably dead
    const float* Wq2 = (const float*)d_in[4];
    const float* bq2 = (const float*)d_in[5];
    const float* Wk2 = (const float*)d_in[8];
    const float* bk2 = (const float*)d_in[9];
    const float* Wv = (const float*)d_in[10];
    const float* bv = (const float*)d_in[11];
    const float* alpha = (const float*)d_in[12];
    float* out = (float*)d_out;

    __half *Xh, *Wt, *QKV, *VhT, *P;
    float *vconst, *bias3, *corr;
    cudaGetSymbolAddress((void**)&Xh, g_Xh);
    cudaGetSymbolAddress((void**)&Wt, g_Wt);
    cudaGetSymbolAddress((void**)&QKV, g_QKV);
    cudaGetSymbolAddress((void**)&VhT, g_VhT);
    cudaGetSymbolAddress((void**)&P, g_P);
    cudaGetSymbolAddress((void**)&vconst, g_vconst);
    cudaGetSymbolAddress((void**)&bias3, g_bias3);
    cudaGetSymbolAddress((void**)&corr, g_corr);

    cudaFuncSetAttribute(gemm_tn<true>, cudaFuncAttributeMaxDynamicSharedMemorySize, SMEM_SZ);
    cudaFuncSetAttribute(gemm_tn<false>, cudaFuncAttributeMaxDynamicSharedMemorySize, SMEM_SZ);

    const int NX = B * S * D;
    const int NW = D * D;

    // 1. conversions (+ weight transposes) + vconst + merged bias
    f2h2_kernel<<<4096, 256>>>((const float2*)X2, (__half2*)Xh, NX / 2);
    {
        dim3 bl(32, 8), gr(32, 32);
        f2ht_kernel<<<gr, bl>>>(Wq2, Wt + 0 * NW);
        f2ht_kernel<<<gr, bl>>>(Wk2, Wt + 1 * NW);
        f2ht_kernel<<<gr, bl>>>(Wv + (long)D * D, Wt + 2 * NW);   // bottom rows
    }
    vconst_kernel<<<dim3(4, B), 256>>>(X1, Wv, bv, vconst);
    biasmerge_kernel<<<dim3(D3 / 256, B), 256>>>(bq2, bk2, vconst, bias3);

    // 2. fused QKV projection: QKV[z][s][0:3D] = Xh[z] @ Wt^T + bias3[z]
    {
        dim3 grid(D3 / BN, S / BM, B);   // 24 x 16 x 8 = 3072 CTAs
        gemm_tn<true><<<grid, 256, SMEM_SZ>>>(Xh, Wt, QKV, D, D, D, D3,
                                              (long)S * D, 0, (long)S * D3,
                                              bias3, D3, 1.0f);
    }

    // 3. correction + V transpose
    corr_kernel<<<dim3(4, B), 256>>>(QKV, alpha, corr);
    transposeV_kernel<<<dim3(S / 64, D / 64, B), 256>>>(QKV, VhT);

    // 4. logits[z][s][s'] = (Q @ K^T)/32 -> g_P as half
    {
        dim3 grid(S / BN, S / BM, B);
        gemm_tn<true><<<grid, 256, SMEM_SZ>>>(QKV, QKV + D, P, D, D3, D3, S,
                                              (long)S * D3, (long)S * D3, (long)S * S,
                                              nullptr, 0, 0.03125f);
    }

    // 5. in-place softmax rows of g_P
    softmax_kernel<<<B * S, 256>>>(P);

    // 6. out[z][s][d] = P[z] @ V[z] + corr[z]
    {
        dim3 grid(D / BN, S / BM, B);
        gemm_tn<false><<<grid, 256, SMEM_SZ>>>(P, VhT, out, S, S, S, D,
                                               (long)S * S, (long)S * D, (long)S * D,
                                               corr, D, 1.0f);
    }
}